// round 16
// baseline (speedup 1.0000x reference)
#include <cuda_runtime.h>
#include <cuda_bf16.h>
#include <cstdint>

#define BATCH 16384
#define HB 120
#define BD 9
#define NSEQ (BATCH*BD)   /* 147456 */
#define NS 32
#define NF 15

// scratch (no cudaMalloc allowed)
__device__ float g_buf1[NSEQ*HB];      // attn2 output, transposed: [(b*9+d)*120 + s]
__device__ float g_xT[HB*NSEQ];        // attn4 output, time-major: [t*NSEQ + n]
__device__ unsigned short g_wbf_hi[4*128*128];  // wq,wk,wv,wo bf16-hi, [m][n(128)][k(128)], zero-padded
__device__ unsigned short g_wbf_lo[4*128*128];  // bf16-lo residuals
__device__ float g_bns[HB*BD];         // BN scale
__device__ float g_bnsh[HB*BD];        // BN shift

__device__ __forceinline__ float phif(float x){ return x>0.0f ? x+1.0f : __expf(x); }
// sigmoid from PRE-HALVED pre-activation a' = a/2:  sig(a)=0.5*tanh(a/2)+0.5
__device__ __forceinline__ float sigp(float xh){
    float t;
    asm("tanh.approx.f32 %0, %1;" : "=f"(t) : "f"(xh));
    return fmaf(0.5f, t, 0.5f);
}
__device__ __forceinline__ float tanht(float x){
    float t;
    asm("tanh.approx.f32 %0, %1;" : "=f"(t) : "f"(x));
    return t;
}

// warp-level bf16 MMA (generic PTX, sm_80+; compiles for plain compute_103)
__device__ __forceinline__ void mma16816(float* d, const uint32_t* a, const uint32_t* b, const float* c){
    asm volatile(
        "mma.sync.aligned.m16n8k16.row.col.f32.bf16.bf16.f32 "
        "{%0,%1,%2,%3}, {%4,%5,%6,%7}, {%8,%9}, {%10,%11,%12,%13};"
        : "=f"(d[0]), "=f"(d[1]), "=f"(d[2]), "=f"(d[3])
        : "r"(a[0]), "r"(a[1]), "r"(a[2]), "r"(a[3]),
          "r"(b[0]), "r"(b[1]),
          "f"(c[0]), "f"(c[1]), "f"(c[2]), "f"(c[3]));
}

// ---------------------------------------------------------------- weights -> bf16 hi/lo + BN precompute
__global__ void k_wbf(const float* __restrict__ wq, const float* __restrict__ wk,
                      const float* __restrict__ wv, const float* __restrict__ wo,
                      const float* __restrict__ bng, const float* __restrict__ bnb,
                      const float* __restrict__ bnm, const float* __restrict__ bnv){
    int idx = blockIdx.x*256 + threadIdx.x;
    if (idx < HB*BD){
        float s = bng[idx] * rsqrtf(bnv[idx] + 1e-5f);
        g_bns[idx] = s;
        g_bnsh[idx] = bnb[idx] - bnm[idx]*s;
    }
    if (idx >= 4*128*128) return;
    int m = idx >> 14, rem = idx & 16383, n = rem >> 7, k = rem & 127;
    const float* W = (m==0)?wq : (m==1)?wk : (m==2)?wv : wo;
    float v = (n < HB && k < HB) ? W[n*HB + k] : 0.0f;
    __nv_bfloat16 h = __float2bfloat16(v);
    g_wbf_hi[idx] = __bfloat16_as_ushort(h);
    g_wbf_lo[idx] = __bfloat16_as_ushort(__float2bfloat16(v - __bfloat162float(h)));
}

// ---------------------------------------------------------------- BN + lin_attn_2 + transpose
__global__ __launch_bounds__(128) void k_attn2(
    const float* __restrict__ x,
    const float* __restrict__ wq, const float* __restrict__ wk,
    const float* __restrict__ wv, const float* __restrict__ wo,
    const float* __restrict__ bo, const float* __restrict__ lg,
    const float* __restrict__ lb)
{
    __shared__ float xs[HB*13], qs[HB*13], ks[HB*13], vs[HB*13];
    __shared__ float wqs[81], wks[81], wvs[81], wos[81];
    __shared__ float kvs[81], ksum[9], bos[9], lgs[9], lbs[9];
    int b = blockIdx.x, tid = threadIdx.x;

    for (int i = tid; i < 1080; i += 128){
        float val = fmaf(x[(size_t)b*1080 + i], g_bns[i], g_bnsh[i]);
        xs[(i/9)*13 + (i%9)] = val;
    }
    if (tid < 81){ wqs[tid]=wq[tid]; wks[tid]=wk[tid]; wvs[tid]=wv[tid]; wos[tid]=wo[tid]; }
    if (tid < 9){ bos[tid]=bo[tid]; lgs[tid]=lg[tid]; lbs[tid]=lb[tid]; }
    __syncthreads();

    if (tid < HB){
        float xr[9];
        #pragma unroll
        for (int d=0; d<9; d++) xr[d] = xs[tid*13+d];
        #pragma unroll
        for (int e=0; e<9; e++){
            float aq=0.f, ak=0.f, av=0.f;
            #pragma unroll
            for (int d=0; d<9; d++){
                aq = fmaf(xr[d], wqs[e*9+d], aq);
                ak = fmaf(xr[d], wks[e*9+d], ak);
                av = fmaf(xr[d], wvs[e*9+d], av);
            }
            qs[tid*13+e] = phif(aq);
            ks[tid*13+e] = phif(ak);
            vs[tid*13+e] = av;
        }
    }
    __syncthreads();

    if (tid < 81){
        int d = tid/9, e = tid%9;
        float a0=0.f, a1=0.f, a2=0.f, a3=0.f;
        #pragma unroll 4
        for (int s=0; s<HB; s+=4){
            a0 = fmaf(ks[(s  )*13+d], vs[(s  )*13+e], a0);
            a1 = fmaf(ks[(s+1)*13+d], vs[(s+1)*13+e], a1);
            a2 = fmaf(ks[(s+2)*13+d], vs[(s+2)*13+e], a2);
            a3 = fmaf(ks[(s+3)*13+d], vs[(s+3)*13+e], a3);
        }
        kvs[tid] = (a0+a1)+(a2+a3);
    } else if (tid < 90){
        int e = tid - 81;
        float a0=0.f, a1=0.f, a2=0.f, a3=0.f;
        #pragma unroll 4
        for (int s=0; s<HB; s+=4){
            a0 += ks[(s  )*13+e];
            a1 += ks[(s+1)*13+e];
            a2 += ks[(s+2)*13+e];
            a3 += ks[(s+3)*13+e];
        }
        ksum[e] = (a0+a1)+(a2+a3);
    }
    __syncthreads();

    if (tid < HB){
        float q[9], o[9];
        float den = 0.f;
        #pragma unroll
        for (int e=0; e<9; e++){ q[e] = qs[tid*13+e]; den = fmaf(q[e], ksum[e], den); }
        float inv = 1.0f / fmaxf(den, 1e-6f);
        #pragma unroll
        for (int e=0; e<9; e++){
            float num = 0.f;
            #pragma unroll
            for (int d=0; d<9; d++) num = fmaf(q[d], kvs[d*9+e], num);
            o[e] = num * inv;
        }
        float y[9]; float mu = 0.f;
        #pragma unroll
        for (int f=0; f<9; f++){
            float acc = bos[f] + o[f];
            #pragma unroll
            for (int e=0; e<9; e++) acc = fmaf(o[e], wos[f*9+e], acc);
            y[f] = acc; mu += acc;
        }
        mu *= (1.0f/9.0f);
        float var = 0.f;
        #pragma unroll
        for (int f=0; f<9; f++){ float dd = y[f]-mu; var = fmaf(dd, dd, var); }
        var *= (1.0f/9.0f);
        float rs = rsqrtf(var + 1e-5f);
        #pragma unroll
        for (int f=0; f<9; f++){
            g_buf1[(size_t)b*1080 + f*HB + tid] = (y[f]-mu)*rs*lgs[f] + lbs[f];
        }
    }
}

// ---------------------------------------------------------------- lin_attn_4 via warp-MMA (bf16 hi/lo)
// S=1 collapse: fac == 1.0 exactly (sum of 120 strictly positive terms >= 1e-6),
// so Q/K projections are dead code and skipped.
#define PL 2176   /* 32 rows * 68 u32 per plane */

__device__ __forceinline__ void proj_mma(
    float acc[4][2][4],
    const uint32_t* Ah, const uint32_t* Al,
    const uint32_t* __restrict__ Bh, const uint32_t* __restrict__ Bl,
    int g, int tg, int w)
{
    #pragma unroll
    for (int nt=0; nt<4; nt++)
        #pragma unroll
        for (int mt=0; mt<2; mt++)
            #pragma unroll
            for (int j=0; j<4; j++) acc[nt][mt][j] = 0.0f;

    #pragma unroll
    for (int kt=0; kt<8; kt++){
        uint32_t axh[2][4], axl[2][4];
        #pragma unroll
        for (int mt=0; mt<2; mt++){
            int Rb = mt*16;
            axh[mt][0]=Ah[(Rb+g  )*68 + kt*8+tg];   axh[mt][1]=Ah[(Rb+g+8)*68 + kt*8+tg];
            axh[mt][2]=Ah[(Rb+g  )*68 + kt*8+tg+4]; axh[mt][3]=Ah[(Rb+g+8)*68 + kt*8+tg+4];
            axl[mt][0]=Al[(Rb+g  )*68 + kt*8+tg];   axl[mt][1]=Al[(Rb+g+8)*68 + kt*8+tg];
            axl[mt][2]=Al[(Rb+g  )*68 + kt*8+tg+4]; axl[mt][3]=Al[(Rb+g+8)*68 + kt*8+tg+4];
        }
        #pragma unroll
        for (int nt=0; nt<4; nt++){
            int n = (w*4+nt)*8 + g;
            uint32_t bh[2], bl[2];
            bh[0]=Bh[n*64 + kt*8 + tg]; bh[1]=Bh[n*64 + kt*8 + tg + 4];
            bl[0]=Bl[n*64 + kt*8 + tg]; bl[1]=Bl[n*64 + kt*8 + tg + 4];
            #pragma unroll
            for (int mt=0; mt<2; mt++){
                mma16816(acc[nt][mt], axh[mt], bh, acc[nt][mt]);
                mma16816(acc[nt][mt], axl[mt], bh, acc[nt][mt]);
                mma16816(acc[nt][mt], axh[mt], bl, acc[nt][mt]);
            }
        }
    }
}

__global__ __launch_bounds__(128, 3) void k_attn4_mma(
    const float* __restrict__ bo4, const float* __restrict__ lg4,
    const float* __restrict__ lb4)
{
    __shared__ __align__(16) uint32_t planes[4*PL];   // xh | xl | vh | vl
    __shared__ float red1[4][32], red2[4][32], mus[32], rss[32];
    __shared__ float sbo[HB], slg[HB], slb[HB];

    uint32_t* xh = planes;        uint32_t* xl = planes +   PL;
    uint32_t* vh = planes + 2*PL; uint32_t* vl = planes + 3*PL;
    unsigned short* xh16 = (unsigned short*)xh;
    unsigned short* xl16 = (unsigned short*)xl;

    int tid = threadIdx.x, w = tid >> 5, lane = tid & 31, g = lane >> 2, tg = lane & 3;
    int base = blockIdx.x * 32;

    for (int i = tid; i < 4*PL; i += 128) planes[i] = 0u;
    if (tid < HB){ sbo[tid] = bo4[tid]; slg[tid] = lg4[tid]; slb[tid] = lb4[tid]; }
    __syncthreads();

    for (int idx = tid; idx < 32*HB; idx += 128){
        int r = idx/HB, d = idx - r*HB;
        float val = g_buf1[(size_t)(base+r)*HB + d];
        __nv_bfloat16 h = __float2bfloat16(val);
        xh16[r*136 + d] = __bfloat16_as_ushort(h);
        xl16[r*136 + d] = __bfloat16_as_ushort(__float2bfloat16(val - __bfloat162float(h)));
    }
    __syncthreads();

    const uint32_t* Wh = (const uint32_t*)g_wbf_hi;
    const uint32_t* Wl = (const uint32_t*)g_wbf_lo;

    // V projection: keep fp32 in regs + write bf16 hi/lo planes for the O-MMA
    float vac[4][2][4];
    proj_mma(vac, xh, xl, Wh + 2*8192, Wl + 2*8192, g, tg, w);
    #pragma unroll
    for (int nt=0; nt<4; nt++)
        #pragma unroll
        for (int mt=0; mt<2; mt++)
            #pragma unroll
            for (int jj=0; jj<2; jj++){
                float v0 = vac[nt][mt][2*jj], v1 = vac[nt][mt][2*jj+1];
                __nv_bfloat16 h0 = __float2bfloat16(v0), h1 = __float2bfloat16(v1);
                uint32_t hp = (uint32_t)__bfloat16_as_ushort(h0) | ((uint32_t)__bfloat16_as_ushort(h1) << 16);
                __nv_bfloat16 l0 = __float2bfloat16(v0 - __bfloat162float(h0));
                __nv_bfloat16 l1 = __float2bfloat16(v1 - __bfloat162float(h1));
                uint32_t lp = (uint32_t)__bfloat16_as_ushort(l0) | ((uint32_t)__bfloat16_as_ushort(l1) << 16);
                int r = mt*16 + g + 8*jj;
                int e2 = w*16 + nt*4 + tg;
                vh[r*68 + e2] = hp;
                vl[r*68 + e2] = lp;
            }
    __syncthreads();

    // O projection
    float oac[4][2][4];
    proj_mma(oac, vh, vl, Wh + 3*8192, Wl + 3*8192, g, tg, w);

    // y = (O + V) + bo  (fac == 1 exactly), then LN over 120 f's
    float s1[2][2] = {{0.f,0.f},{0.f,0.f}}, s2[2][2] = {{0.f,0.f},{0.f,0.f}};
    #pragma unroll
    for (int nt=0; nt<4; nt++)
        #pragma unroll
        for (int mt=0; mt<2; mt++)
            #pragma unroll
            for (int j=0; j<4; j++){
                int f = w*32 + nt*8 + 2*tg + (j&1);
                int fc = (f < HB) ? f : 0;
                float y = (oac[nt][mt][j] + vac[nt][mt][j]) + sbo[fc];
                oac[nt][mt][j] = y;
                if (f < HB){ s1[mt][j>>1] += y; s2[mt][j>>1] += y*y; }
            }
    #pragma unroll
    for (int mt=0; mt<2; mt++)
        #pragma unroll
        for (int jj=0; jj<2; jj++){
            float a = s1[mt][jj], b = s2[mt][jj];
            a += __shfl_xor_sync(0xffffffffu, a, 1);
            a += __shfl_xor_sync(0xffffffffu, a, 2);
            b += __shfl_xor_sync(0xffffffffu, b, 1);
            b += __shfl_xor_sync(0xffffffffu, b, 2);
            if (tg == 0){ red1[w][mt*16 + g + 8*jj] = a; red2[w][mt*16 + g + 8*jj] = b; }
        }
    __syncthreads();
    if (tid < 32){
        float a = red1[0][tid] + red1[1][tid] + red1[2][tid] + red1[3][tid];
        float b = red2[0][tid] + red2[1][tid] + red2[2][tid] + red2[3][tid];
        float mu = a * (1.0f/120.0f);
        float var = b * (1.0f/120.0f) - mu*mu;
        mus[tid] = mu;
        rss[tid] = rsqrtf(var + 1e-5f);
    }
    __syncthreads();

    #pragma unroll
    for (int nt=0; nt<4; nt++)
        #pragma unroll
        for (int mt=0; mt<2; mt++)
            #pragma unroll
            for (int j=0; j<4; j++){
                int f = w*32 + nt*8 + 2*tg + (j&1);
                if (f < HB){
                    int r = mt*16 + g + 8*(j>>1);
                    float yn = (oac[nt][mt][j] - mus[r]) * rss[r];
                    g_xT[(size_t)f*NSEQ + base + r] = yn*slg[f] + slb[f];
                }
            }
}

// ---------------------------------------------------------------- CGLSTM via warp-MMA (bf16 hi/lo)
// Warp-pair decoupling: warps {0,1} own seqs 0-31, warps {2,3} own seqs 32-63.
// Double-buffered S planes (overlay W staging) + ONE named pair-barrier per step
// (bar.sync 1+sh, 64). h-stores batched (round-13 proven pattern).
#define SST 36   /* S row stride in u32; plane = 64*36 = 2304 u32 = 9216 B */
__global__ __launch_bounds__(128, 3) void k_cglstm_mma(
    const float* __restrict__ w_ih, const float* __restrict__ w_hh,
    const float* __restrict__ b_ih, const float* __restrict__ b_hh,
    const float* __restrict__ cg_w, const float* __restrict__ cg_uw,
    const float* __restrict__ cg_ub,
    float* __restrict__ outh)
{
    __shared__ __align__(16) unsigned short sm16[128*72];   // W' staging (18432B) -> 2 S planes
    __shared__ float xs[2][64];
    uint32_t* sm32 = (uint32_t*)sm16;

    int tid = threadIdx.x;
    int warp = tid >> 5, lane = tid & 31;
    int g = lane >> 2, tg = lane & 3;
    int uh = warp & 1, sh = warp >> 1;

    for (int idx = tid; idx < 128*72; idx += 128){
        int r = idx / 72, cc = idx - r*72;
        int gate = r >> 5, j = r & 31;
        float v = 0.0f;
        if (cc < 64){
            int k = cc & 31;
            float w = (gate==0) ? w_hh[j*32+k] : (gate==1) ? w_hh[(32+j)*32+k]
                    : (gate==2) ? w_hh[(64+j)*32+k] : cg_uw[j*32+k];
            if (gate != 2) w *= 0.5f;
            float whi = __bfloat162float(__float2bfloat16(w));
            v = (cc < 32) ? whi : (w - whi);
        }
        sm16[idx] = __bfloat16_as_ushort(__float2bfloat16(v));
    }
    __syncthreads();

    uint32_t afr[4][4][4];
    const int cb2[4] = {0, 8, 16, 24};
    #pragma unroll
    for (int fg = 0; fg < 4; fg++){
        #pragma unroll
        for (int mt = 0; mt < 4; mt++){
            int Rb = mt*32 + uh*16;
            afr[fg][mt][0] = sm32[(Rb+g)*SST   + cb2[fg] + tg];
            afr[fg][mt][1] = sm32[(Rb+g+8)*SST + cb2[fg] + tg];
            afr[fg][mt][2] = sm32[(Rb+g)*SST   + cb2[fg] + tg + 4];
            afr[fg][mt][3] = sm32[(Rb+g+8)*SST + cb2[fg] + tg + 4];
        }
    }

    float wxr[4][2], br[4][2];
    #pragma unroll
    for (int ui = 0; ui < 2; ui++){
        int u = uh*16 + g + ui*8;
        wxr[0][ui] = w_ih[u]*0.5f;     br[0][ui] = (b_ih[u]    + b_hh[u])*0.5f;
        wxr[1][ui] = w_ih[32+u]*0.5f;  br[1][ui] = (b_ih[32+u] + b_hh[32+u])*0.5f;
        wxr[2][ui] = w_ih[64+u];       br[2][ui] =  b_ih[64+u] + b_hh[64+u];
        wxr[3][ui] = cg_w[u]*0.5f;     br[3][ui] =  cg_ub[u]*0.5f;
    }
    __syncthreads();   // W' reads done — overlay S planes

    // zero both S planes; load x(0); prefetch x(1) (uh==0 warp of each pair)
    for (int i = tid; i < 2*64*SST; i += 128) sm32[i] = 0u;
    int base = blockIdx.x * 64;
    if (uh == 0) xs[0][sh*32 + lane] = g_xT[base + sh*32 + lane];
    float xv = (uh == 0) ? g_xT[(size_t)NSEQ + base + sh*32 + lane] : 0.0f;
    __syncthreads();

    float c[16], hn[16];
    #pragma unroll
    for (int i = 0; i < 16; i++){ c[i] = 0.f; hn[i] = 0.f; }
    const float z4[4] = {0.f, 0.f, 0.f, 0.f};
    int p = 0;
    int barid = 1 + sh;

    for (int t = 0; t < HB; t++){
        const uint32_t* Sp = sm32 + p*2304;
        unsigned short* Sw16 = (unsigned short*)(sm32 + (1-p)*2304);
        #pragma unroll
        for (int nt = 0; nt < 4; nt++){
            int rn = sh*32 + nt*8 + g;
            const uint32_t* Srow = &Sp[rn*SST];
            uint32_t b[4][2];
            #pragma unroll
            for (int kt = 0; kt < 4; kt++){
                b[kt][0] = Srow[kt*8 + tg];
                b[kt][1] = Srow[kt*8 + tg + 4];
            }
            float acc[4][4];
            #pragma unroll
            for (int mt = 0; mt < 4; mt++){
                mma16816(acc[mt], afr[0][mt], b[0], z4);
                mma16816(acc[mt], afr[1][mt], b[1], acc[mt]);
                mma16816(acc[mt], afr[2][mt], b[0], acc[mt]);
                mma16816(acc[mt], afr[3][mt], b[1], acc[mt]);
                mma16816(acc[mt], afr[0][mt], b[2], acc[mt]);
                mma16816(acc[mt], afr[1][mt], b[3], acc[mt]);
            }
            #pragma unroll
            for (int j = 0; j < 4; j++){
                int srow = sh*32 + nt*8 + 2*tg + (j & 1);
                float x = xs[p][srow];
                int ui = j >> 1;
                float gi = acc[0][j] + fmaf(wxr[0][ui], x, br[0][ui]);
                float gf = acc[1][j] + fmaf(wxr[1][ui], x, br[1][ui]);
                float gg = acc[2][j] + fmaf(wxr[2][ui], x, br[2][ui]);
                float gc = acc[3][j] + fmaf(wxr[3][ui], x, br[3][ui]);
                int ci = nt*4 + j;
                float cn = sigp(gf)*c[ci] + sigp(gi)*tanht(gg);
                c[ci] = cn;
                hn[ci] = sigp(gc)*tanht(cn);
            }
        }

        // batched h stores into the OTHER plane (no read/write overlap)
        #pragma unroll
        for (int nt = 0; nt < 4; nt++){
            #pragma unroll
            for (int j = 0; j < 4; j++){
                int u = uh*16 + g + ((j >> 1) << 3);
                int srow = sh*32 + nt*8 + 2*tg + (j & 1);
                float h = hn[nt*4 + j];
                __nv_bfloat16 hh = __float2bfloat16(h);
                __nv_bfloat16 hl = __float2bfloat16(h - __bfloat162float(hh));
                Sw16[srow*72 + u]      = __bfloat16_as_ushort(hh);
                Sw16[srow*72 + 32 + u] = __bfloat16_as_ushort(hl);
            }
        }
        if (uh == 0){
            xs[1-p][sh*32 + lane] = xv;
            if (t + 2 < HB) xv = g_xT[(size_t)(t+2)*NSEQ + base + sh*32 + lane];
        }
        asm volatile("bar.sync %0, 64;" :: "r"(barid) : "memory");
        p ^= 1;
    }

    #pragma unroll
    for (int nt = 0; nt < 4; nt++){
        #pragma unroll
        for (int j = 0; j < 4; j++){
            int u = uh*16 + g + ((j >> 1) << 3);
            int srow = sh*32 + nt*8 + 2*tg + (j & 1);
            outh[(size_t)(base + srow)*32 + u] = hn[nt*4 + j];
        }
    }
}

// ---------------------------------------------------------------- conv6/7 + permute + RevIN
// Weights staged TRANSPOSED in smem: w6t[k*60+u], w7t[u*15+f] -> conflict-free LDS.
__global__ __launch_bounds__(160) void k_head(
    const float* __restrict__ w6, const float* __restrict__ b6,
    const float* __restrict__ w7, const float* __restrict__ b7,
    const float* __restrict__ rev_w, const float* __restrict__ rev_b,
    const float* __restrict__ hin, float* __restrict__ enc)
{
    __shared__ float hs[288], w6t[32*60], w7t[60*15], b6s[60], b7s[15];
    __shared__ float t60s[9*60], t135[135];
    __shared__ float smu, sinv;
    __shared__ float part1[5], part2[5];
    int b = blockIdx.x, tid = threadIdx.x;

    for (int i = tid; i < 60*32; i += 160){
        int u = i >> 5, k = i & 31;
        w6t[k*60 + u] = w6[i];
    }
    for (int i = tid; i < 15*60; i += 160){
        int f = i / 60, u = i - f*60;
        w7t[u*15 + f] = w7[i];
    }
    if (tid < 60) b6s[tid] = b6[tid];
    if (tid < 15) b7s[tid] = b7[tid];
    for (int i = tid; i < 288; i += 160) hs[i] = hin[(size_t)b*288 + i];
    __syncthreads();

    for (int i = tid; i < 540; i += 160){
        int dd = i/60, u = i - dd*60;
        float acc = b6s[u];
        #pragma unroll 8
        for (int k=0; k<32; k++) acc = fmaf(w6t[k*60+u], hs[dd*32+k], acc);
        t60s[i] = fmaxf(acc, 0.0f) + __logf(1.0f + __expf(-fabsf(acc)));
    }
    __syncthreads();
    if (tid < 135){
        int dd = tid/15, f = tid - dd*15;
        float acc = b7s[f];
        #pragma unroll 6
        for (int u=0; u<60; u++) acc = fmaf(w7t[u*15+f], t60s[dd*60+u], acc);
        t135[tid] = tanht(acc);
    }
    __syncthreads();
    float v  = (tid < 135) ? t135[tid] : 0.0f;
    float v2 = v*v;
    #pragma unroll
    for (int off=16; off>0; off>>=1){
        v  += __shfl_down_sync(0xffffffffu, v,  off);
        v2 += __shfl_down_sync(0xffffffffu, v2, off);
    }
    if ((tid & 31) == 0){ part1[tid>>5] = v; part2[tid>>5] = v2; }
    __syncthreads();
    if (tid == 0){
        float s1 = 0.f, s2 = 0.f;
        #pragma unroll
        for (int w=0; w<5; w++){ s1 += part1[w]; s2 += part2[w]; }
        float mu = s1 * (1.0f/135.0f);
        float var = fmaxf((s2 - 135.0f*mu*mu) * (1.0f/134.0f), 0.0f);
        float sd = fmaxf(sqrtf(var), 1e-5f);
        smu = mu; sinv = 1.0f/sd;
    }
    __syncthreads();
    if (tid < 135){
        int dp = tid/15, fp = tid - dp*15;
        float yv = t135[fp*9 + dp];       // transpose_8
        enc[(size_t)b*135 + tid] = (yv - smu)*sinv*rev_w[tid] + rev_b[tid];
    }
}

// ---------------------------------------------------------------- launch
extern "C" void kernel_launch(void* const* d_in, const int* in_sizes, int n_in,
                              void* d_out, int out_size)
{
    const float* x     = (const float*)d_in[0];
    const float* bn_g  = (const float*)d_in[1];
    const float* bn_b  = (const float*)d_in[2];
    const float* bn_m  = (const float*)d_in[3];
    const float* bn_v  = (const float*)d_in[4];
    const float* wq2   = (const float*)d_in[5];
    const float* wk2   = (const float*)d_in[6];
    const float* wv2   = (const float*)d_in[7];
    const float* wo2   = (const float*)d_in[8];
    const float* bo2   = (const float*)d_in[9];
    const float* ln2g  = (const float*)d_in[10];
    const float* ln2b  = (const float*)d_in[11];
    const float* wq4   = (const float*)d_in[12];
    const float* wk4   = (const float*)d_in[13];
    const float* wv4   = (const float*)d_in[14];
    const float* wo4   = (const float*)d_in[15];
    const float* bo4   = (const float*)d_in[16];
    const float* ln4g  = (const float*)d_in[17];
    const float* ln4b  = (const float*)d_in[18];
    const float* w_ih  = (const float*)d_in[19];
    const float* w_hh  = (const float*)d_in[20];
    const float* b_ih  = (const float*)d_in[21];
    const float* b_hh  = (const float*)d_in[22];
    const float* cg_w  = (const float*)d_in[23];
    const float* cg_uw = (const float*)d_in[24];
    const float* cg_ub = (const float*)d_in[25];
    const float* w6    = (const float*)d_in[26];
    const float* b6    = (const float*)d_in[27];
    const float* w7    = (const float*)d_in[28];
    const float* b7    = (const float*)d_in[29];
    const float* rev_w = (const float*)d_in[30];
    const float* rev_b = (const float*)d_in[31];
    float* out = (float*)d_out;

    k_wbf<<<(4*128*128 + 255)/256, 256>>>(wq4, wk4, wv4, wo4, bn_g, bn_b, bn_m, bn_v);
    k_attn2<<<BATCH, 128>>>(x, wq2, wk2, wv2, wo2, bo2, ln2g, ln2b);
    k_attn4_mma<<<NSEQ/32, 128>>>(bo4, ln4g, ln4b);
    k_cglstm_mma<<<NSEQ/64, 128>>>(w_ih, w_hh, b_ih, b_hh, cg_w, cg_uw, cg_ub, out);
    k_head<<<BATCH, 160>>>(w6, b6, w7, b7, rev_w, rev_b, out, out + (size_t)BATCH*288);
}

// round 17
// speedup vs baseline: 1.0281x; 1.0281x over previous
#include <cuda_runtime.h>
#include <cuda_bf16.h>
#include <cstdint>

#define BATCH 16384
#define HB 120
#define BD 9
#define NSEQ (BATCH*BD)   /* 147456 */
#define NS 32
#define NF 15

// scratch (no cudaMalloc allowed)
__device__ float g_buf1[NSEQ*HB];      // attn2 output, transposed: [(b*9+d)*120 + s]
__device__ float g_xT[HB*NSEQ];        // attn4 output, time-major: [t*NSEQ + n]
__device__ unsigned short g_wbf_hi[4*128*128];  // wq,wk,wv,wo bf16-hi, [m][n(128)][k(128)], zero-padded
__device__ unsigned short g_wbf_lo[4*128*128];  // bf16-lo residuals
__device__ float g_bns[HB*BD];         // BN scale
__device__ float g_bnsh[HB*BD];        // BN shift

__device__ __forceinline__ float phif(float x){ return x>0.0f ? x+1.0f : __expf(x); }
// sigmoid from PRE-HALVED pre-activation a' = a/2:  sig(a)=0.5*tanh(a/2)+0.5
__device__ __forceinline__ float sigp(float xh){
    float t;
    asm("tanh.approx.f32 %0, %1;" : "=f"(t) : "f"(xh));
    return fmaf(0.5f, t, 0.5f);
}
__device__ __forceinline__ float tanht(float x){
    float t;
    asm("tanh.approx.f32 %0, %1;" : "=f"(t) : "f"(x));
    return t;
}

// warp-level bf16 MMA (generic PTX, sm_80+; compiles for plain compute_103)
__device__ __forceinline__ void mma16816(float* d, const uint32_t* a, const uint32_t* b, const float* c){
    asm volatile(
        "mma.sync.aligned.m16n8k16.row.col.f32.bf16.bf16.f32 "
        "{%0,%1,%2,%3}, {%4,%5,%6,%7}, {%8,%9}, {%10,%11,%12,%13};"
        : "=f"(d[0]), "=f"(d[1]), "=f"(d[2]), "=f"(d[3])
        : "r"(a[0]), "r"(a[1]), "r"(a[2]), "r"(a[3]),
          "r"(b[0]), "r"(b[1]),
          "f"(c[0]), "f"(c[1]), "f"(c[2]), "f"(c[3]));
}

// ---------------------------------------------------------------- weights -> bf16 hi/lo + BN precompute
__global__ void k_wbf(const float* __restrict__ wq, const float* __restrict__ wk,
                      const float* __restrict__ wv, const float* __restrict__ wo,
                      const float* __restrict__ bng, const float* __restrict__ bnb,
                      const float* __restrict__ bnm, const float* __restrict__ bnv){
    int idx = blockIdx.x*256 + threadIdx.x;
    if (idx < HB*BD){
        float s = bng[idx] * rsqrtf(bnv[idx] + 1e-5f);
        g_bns[idx] = s;
        g_bnsh[idx] = bnb[idx] - bnm[idx]*s;
    }
    if (idx >= 4*128*128) return;
    int m = idx >> 14, rem = idx & 16383, n = rem >> 7, k = rem & 127;
    const float* W = (m==0)?wq : (m==1)?wk : (m==2)?wv : wo;
    float v = (n < HB && k < HB) ? W[n*HB + k] : 0.0f;
    __nv_bfloat16 h = __float2bfloat16(v);
    g_wbf_hi[idx] = __bfloat16_as_ushort(h);
    g_wbf_lo[idx] = __bfloat16_as_ushort(__float2bfloat16(v - __bfloat162float(h)));
}

// ---------------------------------------------------------------- BN + lin_attn_2 + transpose
// SMEM halved: q kept in registers (self-read only), x loaded per-row from gmem
// with precomputed BN affine (xs staging pass + one barrier removed).
__global__ __launch_bounds__(128) void k_attn2(
    const float* __restrict__ x,
    const float* __restrict__ wq, const float* __restrict__ wk,
    const float* __restrict__ wv, const float* __restrict__ wo,
    const float* __restrict__ bo, const float* __restrict__ lg,
    const float* __restrict__ lb)
{
    __shared__ float ks[HB*13], vs[HB*13];
    __shared__ float wqs[81], wks[81], wvs[81], wos[81];
    __shared__ float kvs[81], ksum[9], bos[9], lgs[9], lbs[9];
    int b = blockIdx.x, tid = threadIdx.x;

    if (tid < 81){ wqs[tid]=wq[tid]; wks[tid]=wk[tid]; wvs[tid]=wv[tid]; wos[tid]=wo[tid]; }
    if (tid < 9){ bos[tid]=bo[tid]; lgs[tid]=lg[tid]; lbs[tid]=lb[tid]; }
    __syncthreads();

    float q[9];
    if (tid < HB){
        float xr[9];
        #pragma unroll
        for (int d=0; d<9; d++){
            int i = tid*9 + d;
            xr[d] = fmaf(x[(size_t)b*1080 + i], g_bns[i], g_bnsh[i]);
        }
        #pragma unroll
        for (int e=0; e<9; e++){
            float aq=0.f, ak=0.f, av=0.f;
            #pragma unroll
            for (int d=0; d<9; d++){
                aq = fmaf(xr[d], wqs[e*9+d], aq);
                ak = fmaf(xr[d], wks[e*9+d], ak);
                av = fmaf(xr[d], wvs[e*9+d], av);
            }
            q[e] = phif(aq);
            ks[tid*13+e] = phif(ak);
            vs[tid*13+e] = av;
        }
    }
    __syncthreads();

    if (tid < 81){
        int d = tid/9, e = tid%9;
        float a0=0.f, a1=0.f, a2=0.f, a3=0.f;
        #pragma unroll 4
        for (int s=0; s<HB; s+=4){
            a0 = fmaf(ks[(s  )*13+d], vs[(s  )*13+e], a0);
            a1 = fmaf(ks[(s+1)*13+d], vs[(s+1)*13+e], a1);
            a2 = fmaf(ks[(s+2)*13+d], vs[(s+2)*13+e], a2);
            a3 = fmaf(ks[(s+3)*13+d], vs[(s+3)*13+e], a3);
        }
        kvs[tid] = (a0+a1)+(a2+a3);
    } else if (tid < 90){
        int e = tid - 81;
        float a0=0.f, a1=0.f, a2=0.f, a3=0.f;
        #pragma unroll 4
        for (int s=0; s<HB; s+=4){
            a0 += ks[(s  )*13+e];
            a1 += ks[(s+1)*13+e];
            a2 += ks[(s+2)*13+e];
            a3 += ks[(s+3)*13+e];
        }
        ksum[e] = (a0+a1)+(a2+a3);
    }
    __syncthreads();

    if (tid < HB){
        float o[9];
        float den = 0.f;
        #pragma unroll
        for (int e=0; e<9; e++) den = fmaf(q[e], ksum[e], den);
        float inv = 1.0f / fmaxf(den, 1e-6f);
        #pragma unroll
        for (int e=0; e<9; e++){
            float num = 0.f;
            #pragma unroll
            for (int d=0; d<9; d++) num = fmaf(q[d], kvs[d*9+e], num);
            o[e] = num * inv;
        }
        float y[9]; float mu = 0.f;
        #pragma unroll
        for (int f=0; f<9; f++){
            float acc = bos[f] + o[f];
            #pragma unroll
            for (int e=0; e<9; e++) acc = fmaf(o[e], wos[f*9+e], acc);
            y[f] = acc; mu += acc;
        }
        mu *= (1.0f/9.0f);
        float var = 0.f;
        #pragma unroll
        for (int f=0; f<9; f++){ float dd = y[f]-mu; var = fmaf(dd, dd, var); }
        var *= (1.0f/9.0f);
        float rs = rsqrtf(var + 1e-5f);
        #pragma unroll
        for (int f=0; f<9; f++){
            g_buf1[(size_t)b*1080 + f*HB + tid] = (y[f]-mu)*rs*lgs[f] + lbs[f];
        }
    }
}

// ---------------------------------------------------------------- lin_attn_4 via warp-MMA (bf16 hi/lo)
// S=1 collapse: fac == 1.0 exactly (sum of 120 strictly positive terms >= 1e-6),
// so Q/K projections are dead code and skipped.
#define PL 2176   /* 32 rows * 68 u32 per plane */

__device__ __forceinline__ void proj_mma(
    float acc[4][2][4],
    const uint32_t* Ah, const uint32_t* Al,
    const uint32_t* __restrict__ Bh, const uint32_t* __restrict__ Bl,
    int g, int tg, int w)
{
    #pragma unroll
    for (int nt=0; nt<4; nt++)
        #pragma unroll
        for (int mt=0; mt<2; mt++)
            #pragma unroll
            for (int j=0; j<4; j++) acc[nt][mt][j] = 0.0f;

    #pragma unroll
    for (int kt=0; kt<8; kt++){
        uint32_t axh[2][4], axl[2][4];
        #pragma unroll
        for (int mt=0; mt<2; mt++){
            int Rb = mt*16;
            axh[mt][0]=Ah[(Rb+g  )*68 + kt*8+tg];   axh[mt][1]=Ah[(Rb+g+8)*68 + kt*8+tg];
            axh[mt][2]=Ah[(Rb+g  )*68 + kt*8+tg+4]; axh[mt][3]=Ah[(Rb+g+8)*68 + kt*8+tg+4];
            axl[mt][0]=Al[(Rb+g  )*68 + kt*8+tg];   axl[mt][1]=Al[(Rb+g+8)*68 + kt*8+tg];
            axl[mt][2]=Al[(Rb+g  )*68 + kt*8+tg+4]; axl[mt][3]=Al[(Rb+g+8)*68 + kt*8+tg+4];
        }
        #pragma unroll
        for (int nt=0; nt<4; nt++){
            int n = (w*4+nt)*8 + g;
            uint32_t bh[2], bl[2];
            bh[0]=Bh[n*64 + kt*8 + tg]; bh[1]=Bh[n*64 + kt*8 + tg + 4];
            bl[0]=Bl[n*64 + kt*8 + tg]; bl[1]=Bl[n*64 + kt*8 + tg + 4];
            #pragma unroll
            for (int mt=0; mt<2; mt++){
                mma16816(acc[nt][mt], axh[mt], bh, acc[nt][mt]);
                mma16816(acc[nt][mt], axl[mt], bh, acc[nt][mt]);
                mma16816(acc[nt][mt], axh[mt], bl, acc[nt][mt]);
            }
        }
    }
}

__global__ __launch_bounds__(128, 3) void k_attn4_mma(
    const float* __restrict__ bo4, const float* __restrict__ lg4,
    const float* __restrict__ lb4)
{
    __shared__ __align__(16) uint32_t planes[4*PL];   // xh | xl | vh | vl
    __shared__ float red1[4][32], red2[4][32], mus[32], rss[32];
    __shared__ float sbo[HB], slg[HB], slb[HB];

    uint32_t* xh = planes;        uint32_t* xl = planes +   PL;
    uint32_t* vh = planes + 2*PL; uint32_t* vl = planes + 3*PL;
    unsigned short* xh16 = (unsigned short*)xh;
    unsigned short* xl16 = (unsigned short*)xl;

    int tid = threadIdx.x, w = tid >> 5, lane = tid & 31, g = lane >> 2, tg = lane & 3;
    int base = blockIdx.x * 32;

    for (int i = tid; i < 4*PL; i += 128) planes[i] = 0u;
    if (tid < HB){ sbo[tid] = bo4[tid]; slg[tid] = lg4[tid]; slb[tid] = lb4[tid]; }
    __syncthreads();

    for (int idx = tid; idx < 32*HB; idx += 128){
        int r = idx/HB, d = idx - r*HB;
        float val = g_buf1[(size_t)(base+r)*HB + d];
        __nv_bfloat16 h = __float2bfloat16(val);
        xh16[r*136 + d] = __bfloat16_as_ushort(h);
        xl16[r*136 + d] = __bfloat16_as_ushort(__float2bfloat16(val - __bfloat162float(h)));
    }
    __syncthreads();

    const uint32_t* Wh = (const uint32_t*)g_wbf_hi;
    const uint32_t* Wl = (const uint32_t*)g_wbf_lo;

    // V projection: keep fp32 in regs + write bf16 hi/lo planes for the O-MMA
    float vac[4][2][4];
    proj_mma(vac, xh, xl, Wh + 2*8192, Wl + 2*8192, g, tg, w);
    #pragma unroll
    for (int nt=0; nt<4; nt++)
        #pragma unroll
        for (int mt=0; mt<2; mt++)
            #pragma unroll
            for (int jj=0; jj<2; jj++){
                float v0 = vac[nt][mt][2*jj], v1 = vac[nt][mt][2*jj+1];
                __nv_bfloat16 h0 = __float2bfloat16(v0), h1 = __float2bfloat16(v1);
                uint32_t hp = (uint32_t)__bfloat16_as_ushort(h0) | ((uint32_t)__bfloat16_as_ushort(h1) << 16);
                __nv_bfloat16 l0 = __float2bfloat16(v0 - __bfloat162float(h0));
                __nv_bfloat16 l1 = __float2bfloat16(v1 - __bfloat162float(h1));
                uint32_t lp = (uint32_t)__bfloat16_as_ushort(l0) | ((uint32_t)__bfloat16_as_ushort(l1) << 16);
                int r = mt*16 + g + 8*jj;
                int e2 = w*16 + nt*4 + tg;
                vh[r*68 + e2] = hp;
                vl[r*68 + e2] = lp;
            }
    __syncthreads();

    // O projection
    float oac[4][2][4];
    proj_mma(oac, vh, vl, Wh + 3*8192, Wl + 3*8192, g, tg, w);

    // y = (O + V) + bo  (fac == 1 exactly), then LN over 120 f's
    float s1[2][2] = {{0.f,0.f},{0.f,0.f}}, s2[2][2] = {{0.f,0.f},{0.f,0.f}};
    #pragma unroll
    for (int nt=0; nt<4; nt++)
        #pragma unroll
        for (int mt=0; mt<2; mt++)
            #pragma unroll
            for (int j=0; j<4; j++){
                int f = w*32 + nt*8 + 2*tg + (j&1);
                int fc = (f < HB) ? f : 0;
                float y = (oac[nt][mt][j] + vac[nt][mt][j]) + sbo[fc];
                oac[nt][mt][j] = y;
                if (f < HB){ s1[mt][j>>1] += y; s2[mt][j>>1] += y*y; }
            }
    #pragma unroll
    for (int mt=0; mt<2; mt++)
        #pragma unroll
        for (int jj=0; jj<2; jj++){
            float a = s1[mt][jj], b = s2[mt][jj];
            a += __shfl_xor_sync(0xffffffffu, a, 1);
            a += __shfl_xor_sync(0xffffffffu, a, 2);
            b += __shfl_xor_sync(0xffffffffu, b, 1);
            b += __shfl_xor_sync(0xffffffffu, b, 2);
            if (tg == 0){ red1[w][mt*16 + g + 8*jj] = a; red2[w][mt*16 + g + 8*jj] = b; }
        }
    __syncthreads();
    if (tid < 32){
        float a = red1[0][tid] + red1[1][tid] + red1[2][tid] + red1[3][tid];
        float b = red2[0][tid] + red2[1][tid] + red2[2][tid] + red2[3][tid];
        float mu = a * (1.0f/120.0f);
        float var = b * (1.0f/120.0f) - mu*mu;
        mus[tid] = mu;
        rss[tid] = rsqrtf(var + 1e-5f);
    }
    __syncthreads();

    #pragma unroll
    for (int nt=0; nt<4; nt++)
        #pragma unroll
        for (int mt=0; mt<2; mt++)
            #pragma unroll
            for (int j=0; j<4; j++){
                int f = w*32 + nt*8 + 2*tg + (j&1);
                if (f < HB){
                    int r = mt*16 + g + 8*(j>>1);
                    float yn = (oac[nt][mt][j] - mus[r]) * rss[r];
                    g_xT[(size_t)f*NSEQ + base + r] = yn*slg[f] + slb[f];
                }
            }
}

// ---------------------------------------------------------------- CGLSTM via warp-MMA (bf16 hi/lo)
// FROZEN round-13 variant: single S plane, batched h-stores, two block barriers/step.
#define SST 36   /* S row stride in u32 */
__global__ __launch_bounds__(128, 3) void k_cglstm_mma(
    const float* __restrict__ w_ih, const float* __restrict__ w_hh,
    const float* __restrict__ b_ih, const float* __restrict__ b_hh,
    const float* __restrict__ cg_w, const float* __restrict__ cg_uw,
    const float* __restrict__ cg_ub,
    float* __restrict__ outh)
{
    __shared__ __align__(16) unsigned short sm16[128*72];   // W' staging (18KB), later S overlay
    __shared__ float xs[64];
    uint32_t* sm32 = (uint32_t*)sm16;

    int tid = threadIdx.x;
    int warp = tid >> 5, lane = tid & 31;
    int g = lane >> 2, tg = lane & 3;
    int uh = warp & 1, sh = warp >> 1;

    for (int idx = tid; idx < 128*72; idx += 128){
        int r = idx / 72, cc = idx - r*72;
        int gate = r >> 5, j = r & 31;
        float v = 0.0f;
        if (cc < 64){
            int k = cc & 31;
            float w = (gate==0) ? w_hh[j*32+k] : (gate==1) ? w_hh[(32+j)*32+k]
                    : (gate==2) ? w_hh[(64+j)*32+k] : cg_uw[j*32+k];
            if (gate != 2) w *= 0.5f;
            float whi = __bfloat162float(__float2bfloat16(w));
            v = (cc < 32) ? whi : (w - whi);
        }
        sm16[idx] = __bfloat16_as_ushort(__float2bfloat16(v));
    }
    __syncthreads();

    uint32_t afr[4][4][4];
    const int cb2[4] = {0, 8, 16, 24};
    #pragma unroll
    for (int fg = 0; fg < 4; fg++){
        #pragma unroll
        for (int mt = 0; mt < 4; mt++){
            int Rb = mt*32 + uh*16;
            afr[fg][mt][0] = sm32[(Rb+g)*SST   + cb2[fg] + tg];
            afr[fg][mt][1] = sm32[(Rb+g+8)*SST + cb2[fg] + tg];
            afr[fg][mt][2] = sm32[(Rb+g)*SST   + cb2[fg] + tg + 4];
            afr[fg][mt][3] = sm32[(Rb+g+8)*SST + cb2[fg] + tg + 4];
        }
    }

    float wxr[4][2], br[4][2];
    #pragma unroll
    for (int ui = 0; ui < 2; ui++){
        int u = uh*16 + g + ui*8;
        wxr[0][ui] = w_ih[u]*0.5f;     br[0][ui] = (b_ih[u]    + b_hh[u])*0.5f;
        wxr[1][ui] = w_ih[32+u]*0.5f;  br[1][ui] = (b_ih[32+u] + b_hh[32+u])*0.5f;
        wxr[2][ui] = w_ih[64+u];       br[2][ui] =  b_ih[64+u] + b_hh[64+u];
        wxr[3][ui] = cg_w[u]*0.5f;     br[3][ui] =  cg_ub[u]*0.5f;
    }
    __syncthreads();

    for (int i = tid; i < 64*SST; i += 128) sm32[i] = 0u;
    int base = blockIdx.x * 64;
    if (tid < 64) xs[tid] = g_xT[base + tid];
    float xv = (tid < 64) ? g_xT[(size_t)NSEQ + base + tid] : 0.0f;
    __syncthreads();

    float c[16], hn[16];
    #pragma unroll
    for (int i = 0; i < 16; i++){ c[i] = 0.f; hn[i] = 0.f; }
    const float z4[4] = {0.f, 0.f, 0.f, 0.f};

    for (int t = 0; t < HB; t++){
        #pragma unroll
        for (int nt = 0; nt < 4; nt++){
            int rn = sh*32 + nt*8 + g;
            const uint32_t* Srow = &sm32[rn*SST];
            uint32_t b[4][2];
            #pragma unroll
            for (int kt = 0; kt < 4; kt++){
                b[kt][0] = Srow[kt*8 + tg];
                b[kt][1] = Srow[kt*8 + tg + 4];
            }
            float acc[4][4];
            #pragma unroll
            for (int mt = 0; mt < 4; mt++){
                mma16816(acc[mt], afr[0][mt], b[0], z4);
                mma16816(acc[mt], afr[1][mt], b[1], acc[mt]);
                mma16816(acc[mt], afr[2][mt], b[0], acc[mt]);
                mma16816(acc[mt], afr[3][mt], b[1], acc[mt]);
                mma16816(acc[mt], afr[0][mt], b[2], acc[mt]);
                mma16816(acc[mt], afr[1][mt], b[3], acc[mt]);
            }
            #pragma unroll
            for (int j = 0; j < 4; j++){
                int srow = sh*32 + nt*8 + 2*tg + (j & 1);
                float x = xs[srow];
                int ui = j >> 1;
                float gi = acc[0][j] + fmaf(wxr[0][ui], x, br[0][ui]);
                float gf = acc[1][j] + fmaf(wxr[1][ui], x, br[1][ui]);
                float gg = acc[2][j] + fmaf(wxr[2][ui], x, br[2][ui]);
                float gc = acc[3][j] + fmaf(wxr[3][ui], x, br[3][ui]);
                int ci = nt*4 + j;
                float cn = sigp(gf)*c[ci] + sigp(gi)*tanht(gg);
                c[ci] = cn;
                hn[ci] = sigp(gc)*tanht(cn);
            }
        }
        __syncthreads();

        #pragma unroll
        for (int nt = 0; nt < 4; nt++){
            #pragma unroll
            for (int j = 0; j < 4; j++){
                int u = uh*16 + g + ((j >> 1) << 3);
                int srow = sh*32 + nt*8 + 2*tg + (j & 1);
                float h = hn[nt*4 + j];
                __nv_bfloat16 hh = __float2bfloat16(h);
                __nv_bfloat16 hl = __float2bfloat16(h - __bfloat162float(hh));
                sm16[srow*72 + u]      = __bfloat16_as_ushort(hh);
                sm16[srow*72 + 32 + u] = __bfloat16_as_ushort(hl);
            }
        }
        if (tid < 64) xs[tid] = xv;
        if (t + 2 < HB && tid < 64) xv = g_xT[(size_t)(t+2)*NSEQ + base + tid];
        __syncthreads();
    }

    #pragma unroll
    for (int nt = 0; nt < 4; nt++){
        #pragma unroll
        for (int j = 0; j < 4; j++){
            int u = uh*16 + g + ((j >> 1) << 3);
            int srow = sh*32 + nt*8 + 2*tg + (j & 1);
            outh[(size_t)(base + srow)*32 + u] = hn[nt*4 + j];
        }
    }
}

// ---------------------------------------------------------------- conv6/7 + permute + RevIN
// Weights staged TRANSPOSED in smem: w6t[k*60+u], w7t[u*15+f] -> conflict-free LDS.
__global__ __launch_bounds__(160) void k_head(
    const float* __restrict__ w6, const float* __restrict__ b6,
    const float* __restrict__ w7, const float* __restrict__ b7,
    const float* __restrict__ rev_w, const float* __restrict__ rev_b,
    const float* __restrict__ hin, float* __restrict__ enc)
{
    __shared__ float hs[288], w6t[32*60], w7t[60*15], b6s[60], b7s[15];
    __shared__ float t60s[9*60], t135[135];
    __shared__ float smu, sinv;
    __shared__ float part1[5], part2[5];
    int b = blockIdx.x, tid = threadIdx.x;

    for (int i = tid; i < 60*32; i += 160){
        int u = i >> 5, k = i & 31;
        w6t[k*60 + u] = w6[i];
    }
    for (int i = tid; i < 15*60; i += 160){
        int f = i / 60, u = i - f*60;
        w7t[u*15 + f] = w7[i];
    }
    if (tid < 60) b6s[tid] = b6[tid];
    if (tid < 15) b7s[tid] = b7[tid];
    for (int i = tid; i < 288; i += 160) hs[i] = hin[(size_t)b*288 + i];
    __syncthreads();

    for (int i = tid; i < 540; i += 160){
        int dd = i/60, u = i - dd*60;
        float acc = b6s[u];
        #pragma unroll 8
        for (int k=0; k<32; k++) acc = fmaf(w6t[k*60+u], hs[dd*32+k], acc);
        t60s[i] = fmaxf(acc, 0.0f) + __logf(1.0f + __expf(-fabsf(acc)));
    }
    __syncthreads();
    if (tid < 135){
        int dd = tid/15, f = tid - dd*15;
        float acc = b7s[f];
        #pragma unroll 6
        for (int u=0; u<60; u++) acc = fmaf(w7t[u*15+f], t60s[dd*60+u], acc);
        t135[tid] = tanht(acc);
    }
    __syncthreads();
    float v  = (tid < 135) ? t135[tid] : 0.0f;
    float v2 = v*v;
    #pragma unroll
    for (int off=16; off>0; off>>=1){
        v  += __shfl_down_sync(0xffffffffu, v,  off);
        v2 += __shfl_down_sync(0xffffffffu, v2, off);
    }
    if ((tid & 31) == 0){ part1[tid>>5] = v; part2[tid>>5] = v2; }
    __syncthreads();
    if (tid == 0){
        float s1 = 0.f, s2 = 0.f;
        #pragma unroll
        for (int w=0; w<5; w++){ s1 += part1[w]; s2 += part2[w]; }
        float mu = s1 * (1.0f/135.0f);
        float var = fmaxf((s2 - 135.0f*mu*mu) * (1.0f/134.0f), 0.0f);
        float sd = fmaxf(sqrtf(var), 1e-5f);
        smu = mu; sinv = 1.0f/sd;
    }
    __syncthreads();
    if (tid < 135){
        int dp = tid/15, fp = tid - dp*15;
        float yv = t135[fp*9 + dp];       // transpose_8
        enc[(size_t)b*135 + tid] = (yv - smu)*sinv*rev_w[tid] + rev_b[tid];
    }
}

// ---------------------------------------------------------------- launch
extern "C" void kernel_launch(void* const* d_in, const int* in_sizes, int n_in,
                              void* d_out, int out_size)
{
    const float* x     = (const float*)d_in[0];
    const float* bn_g  = (const float*)d_in[1];
    const float* bn_b  = (const float*)d_in[2];
    const float* bn_m  = (const float*)d_in[3];
    const float* bn_v  = (const float*)d_in[4];
    const float* wq2   = (const float*)d_in[5];
    const float* wk2   = (const float*)d_in[6];
    const float* wv2   = (const float*)d_in[7];
    const float* wo2   = (const float*)d_in[8];
    const float* bo2   = (const float*)d_in[9];
    const float* ln2g  = (const float*)d_in[10];
    const float* ln2b  = (const float*)d_in[11];
    const float* wq4   = (const float*)d_in[12];
    const float* wk4   = (const float*)d_in[13];
    const float* wv4   = (const float*)d_in[14];
    const float* wo4   = (const float*)d_in[15];
    const float* bo4   = (const float*)d_in[16];
    const float* ln4g  = (const float*)d_in[17];
    const float* ln4b  = (const float*)d_in[18];
    const float* w_ih  = (const float*)d_in[19];
    const float* w_hh  = (const float*)d_in[20];
    const float* b_ih  = (const float*)d_in[21];
    const float* b_hh  = (const float*)d_in[22];
    const float* cg_w  = (const float*)d_in[23];
    const float* cg_uw = (const float*)d_in[24];
    const float* cg_ub = (const float*)d_in[25];
    const float* w6    = (const float*)d_in[26];
    const float* b6    = (const float*)d_in[27];
    const float* w7    = (const float*)d_in[28];
    const float* b7    = (const float*)d_in[29];
    const float* rev_w = (const float*)d_in[30];
    const float* rev_b = (const float*)d_in[31];
    float* out = (float*)d_out;

    k_wbf<<<(4*128*128 + 255)/256, 256>>>(wq4, wk4, wv4, wo4, bn_g, bn_b, bn_m, bn_v);
    k_attn2<<<BATCH, 128>>>(x, wq2, wk2, wv2, wo2, bo2, ln2g, ln2b);
    k_attn4_mma<<<NSEQ/32, 128>>>(bo4, ln4g, ln4b);
    k_cglstm_mma<<<NSEQ/64, 128>>>(w_ih, w_hh, b_ih, b_hh, cg_w, cg_uw, cg_ub, out);
    k_head<<<BATCH, 160>>>(w6, b6, w7, b7, rev_w, rev_b, out, out + (size_t)BATCH*288);
}